// round 2
// baseline (speedup 1.0000x reference)
#include <cuda_runtime.h>
#include <cuda_bf16.h>
#include <math.h>

// Problem constants (LocalSubgraphTransformer)
#define S_   2048
#define K_   32
#define H_   256
#define NH_  8
#define DH_  32
#define L_   4
#define ED_  16
#define FFN_ 512
#define EPS_ 64
#define E_   (S_*EPS_)
#define BUFLD 768

// 64 MB scratch for the edge bias [S, NH, K, K]
__device__ float g_bias[(size_t)S_ * NH_ * K_ * K_];

// ---------------------------------------------------------------------------
// Kernel A: per-subgraph edge bias via shared-memory scatter-add
// bias[s, h, src, dst] += ea[e] . edge_W[h] + edge_b[h]   for e in subgraph s
// ---------------------------------------------------------------------------
__global__ __launch_bounds__(256) void edge_bias_kernel(
    const float* __restrict__ ea, const int* __restrict__ eidx,
    const float* __restrict__ eW, const float* __restrict__ eb)
{
    __shared__ float sb[NH_*K_*K_];   // 8192 floats
    __shared__ float sa[EPS_*ED_];    // 1024 floats
    __shared__ float sw[NH_*ED_];
    __shared__ float sbv[NH_];
    const int s = blockIdx.x, tid = threadIdx.x;

    if (tid < NH_*ED_) sw[tid] = eW[tid];
    if (tid < NH_)     sbv[tid] = eb[tid];
    for (int i = tid; i < EPS_*ED_;  i += 256) sa[i] = ea[(size_t)s*EPS_*ED_ + i];
    for (int i = tid; i < NH_*K_*K_; i += 256) sb[i] = 0.f;
    __syncthreads();

    #pragma unroll
    for (int t = tid; t < EPS_*NH_; t += 256) {
        const int i  = t >> 3;    // edge within subgraph
        const int hh = t & 7;     // head
        float p = sbv[hh];
        #pragma unroll
        for (int d = 0; d < ED_; d++) p = fmaf(sa[i*ED_+d], sw[hh*ED_+d], p);
        const int e  = s*EPS_ + i;
        const int sr = eidx[e];
        const int ds = eidx[E_ + e];
        atomicAdd(&sb[hh*K_*K_ + sr*K_ + ds], p);
    }
    __syncthreads();
    for (int i = tid; i < NH_*K_*K_; i += 256)
        g_bias[(size_t)s*NH_*K_*K_ + i] = sb[i];
}

// ---------------------------------------------------------------------------
// Kernel B: fused 4-layer transformer, one CTA per subgraph
// ---------------------------------------------------------------------------
// smem layout (floats)
#define OFF_X    0
#define OFF_XN   8192
#define OFF_BUF  16384   /* 24576 floats: qkv [32][768] or ffn hidden [32][512] */
#define OFF_BIAS 40960   /* 8448 floats: transposed bias [h][k][q] ld 33 */
#define OFF_KM   49408   /* 32: additive key mask (0 / -1e30) */
#define OFF_V01  49440   /* 32: valid as 0/1 float */
#define SMEM2_FLOATS 49472

// C[32,N] = A[32,KA] @ W[N,KA]^T + bias ; MODE 0: store, 1: store+relu, 2: dst += C
template<int N, int KA, int MODE>
__device__ __forceinline__ void mm32(const float* A, const float* __restrict__ W,
                                     const float* __restrict__ bias, float* dst, int tid)
{
    const int rg = tid >> 5;   // warp id -> rows rg*4 .. rg*4+3 (broadcast A loads)
    const int cg = tid & 31;   // lane    -> 4 columns
    for (int pass = 0; pass < N/128; pass++) {
        const int c0 = pass*128 + cg*4;
        float acc[4][4];
        #pragma unroll
        for (int i = 0; i < 4; i++) {
            const float bv = bias[c0+i];
            #pragma unroll
            for (int j = 0; j < 4; j++) acc[j][i] = bv;
        }
        const float* Wp = W + (size_t)c0*KA;
        #pragma unroll 2
        for (int k = 0; k < KA; k += 4) {
            float4 a[4];
            #pragma unroll
            for (int j = 0; j < 4; j++)
                a[j] = *(const float4*)(A + (rg*4+j)*KA + k);
            #pragma unroll
            for (int i = 0; i < 4; i++) {
                const float4 w = *(const float4*)(Wp + i*KA + k);
                #pragma unroll
                for (int j = 0; j < 4; j++) {
                    acc[j][i] = fmaf(a[j].x, w.x, acc[j][i]);
                    acc[j][i] = fmaf(a[j].y, w.y, acc[j][i]);
                    acc[j][i] = fmaf(a[j].z, w.z, acc[j][i]);
                    acc[j][i] = fmaf(a[j].w, w.w, acc[j][i]);
                }
            }
        }
        #pragma unroll
        for (int j = 0; j < 4; j++) {
            float4 r = make_float4(acc[j][0], acc[j][1], acc[j][2], acc[j][3]);
            if (MODE == 1) {
                r.x = fmaxf(r.x, 0.f); r.y = fmaxf(r.y, 0.f);
                r.z = fmaxf(r.z, 0.f); r.w = fmaxf(r.w, 0.f);
            }
            float4* p = (float4*)(dst + (rg*4+j)*N + c0);
            if (MODE == 2) {
                float4 o = *p;
                r.x += o.x; r.y += o.y; r.z += o.z; r.w += o.w;
            }
            *p = r;
        }
    }
}

// LayerNorm over 32 rows of H_: warp w handles rows w*4..w*4+3
__device__ __forceinline__ void ln32(const float* src, float* dst,
                                     const float* __restrict__ g,
                                     const float* __restrict__ b, int tid)
{
    const int w = tid >> 5, lane = tid & 31;
    #pragma unroll
    for (int j = 0; j < 4; j++) {
        const int r = w*4 + j;
        float sum = 0.f, sq = 0.f;
        #pragma unroll
        for (int i = 0; i < 8; i++) {
            const float v = src[r*H_ + lane + i*32];
            sum += v; sq = fmaf(v, v, sq);
        }
        #pragma unroll
        for (int o = 16; o > 0; o >>= 1) {
            sum += __shfl_xor_sync(0xffffffffu, sum, o);
            sq  += __shfl_xor_sync(0xffffffffu, sq,  o);
        }
        const float mu   = sum * (1.f/H_);
        const float var  = sq * (1.f/H_) - mu*mu;
        const float rstd = rsqrtf(var + 1e-5f);
        #pragma unroll
        for (int i = 0; i < 8; i++) {
            const int c = lane + i*32;
            const float v = src[r*H_ + c];
            dst[r*H_ + c] = fmaf((v - mu)*rstd, g[c], b[c]);
        }
    }
}

// Attention: warp = head, lane = query row. qkv in BUF (ld 768), o -> XN (ld 256)
__device__ __forceinline__ void attn32(const float* BUF_, const float* BS,
                                       const float* KM, float* XN_, int tid)
{
    const int head = tid >> 5, lane = tid & 31;
    const float scale = 0.17677669529663687f;  // 1/sqrt(32)

    float4 q4[8];
    const float4* qp = (const float4*)(BUF_ + lane*BUFLD + head*32);
    #pragma unroll
    for (int j = 0; j < 8; j++) q4[j] = qp[j];

    float sc[32];
    float m = -3.0e38f;
    #pragma unroll
    for (int kr = 0; kr < 32; kr++) {
        const float4* kp = (const float4*)(BUF_ + kr*BUFLD + H_ + head*32);
        float s = 0.f;
        #pragma unroll
        for (int j = 0; j < 8; j++) {
            const float4 kk = kp[j];
            s = fmaf(q4[j].x, kk.x, s); s = fmaf(q4[j].y, kk.y, s);
            s = fmaf(q4[j].z, kk.z, s); s = fmaf(q4[j].w, kk.w, s);
        }
        s = fmaf(s, scale, BS[head*1056 + kr*33 + lane]) + KM[kr];
        sc[kr] = s;
        m = fmaxf(m, s);
    }
    float den = 0.f;
    #pragma unroll
    for (int kr = 0; kr < 32; kr++) { const float e = __expf(sc[kr] - m); sc[kr] = e; den += e; }
    const float inv = 1.f / den;
    #pragma unroll
    for (int kr = 0; kr < 32; kr++) sc[kr] *= inv;

    #pragma unroll
    for (int dg = 0; dg < 8; dg++) {
        float4 acc = make_float4(0.f, 0.f, 0.f, 0.f);
        #pragma unroll
        for (int kr = 0; kr < 32; kr++) {
            const float4 v4 = *(const float4*)(BUF_ + kr*BUFLD + 2*H_ + head*32 + dg*4);
            const float w = sc[kr];
            acc.x = fmaf(w, v4.x, acc.x); acc.y = fmaf(w, v4.y, acc.y);
            acc.z = fmaf(w, v4.z, acc.z); acc.w = fmaf(w, v4.w, acc.w);
        }
        *(float4*)(XN_ + lane*H_ + head*32 + dg*4) = acc;
    }
}

__global__ __launch_bounds__(256, 1) void xf_kernel(
    const float* __restrict__ h, const void* __restrict__ validp,
    const float* __restrict__ ln1g, const float* __restrict__ ln1b,
    const float* __restrict__ qkvW, const float* __restrict__ qkvb,
    const float* __restrict__ outW, const float* __restrict__ outb,
    const float* __restrict__ ln2g, const float* __restrict__ ln2b,
    const float* __restrict__ ff1W, const float* __restrict__ ff1b,
    const float* __restrict__ ff2W, const float* __restrict__ ff2b,
    const float* __restrict__ fng, const float* __restrict__ fnb,
    float* __restrict__ out)
{
    extern __shared__ float sm[];
    float* X   = sm + OFF_X;
    float* XN  = sm + OFF_XN;
    float* BUF = sm + OFF_BUF;
    float* BS  = sm + OFF_BIAS;
    float* KM  = sm + OFF_KM;
    float* V01 = sm + OFF_V01;
    const int s = blockIdx.x, tid = threadIdx.x;

    // Detect 'valid' encoding: byte bools vs 32-bit (int32 0/1 or float32 0.0/1.0).
    // For 32-bit encodings, bytes at offset%4==1 of the first words are always 0.
    const unsigned char* vb = (const unsigned char*)validp;
    bool bytemode = false;
    #pragma unroll
    for (int i = 1; i < 128; i += 4) bytemode |= (vb[i] != 0);

    if (tid < K_) {
        bool v;
        if (bytemode) v = vb[s*K_ + tid] != 0;
        else          v = ((const unsigned int*)validp)[s*K_ + tid] != 0u;
        KM[tid]  = v ? 0.f : -1e30f;
        V01[tid] = v ? 1.f : 0.f;
    }
    for (int i = tid; i < K_*H_; i += 256) X[i] = h[(size_t)s*K_*H_ + i];
    // bias: global [h][q][k] -> smem transposed [h][k][q], ld 33 (conflict-free)
    for (int i = tid; i < NH_*K_*K_; i += 256) {
        const int hh = i >> 10, q = (i >> 5) & 31, kr = i & 31;
        BS[hh*1056 + kr*33 + q] = g_bias[(size_t)s*NH_*K_*K_ + i];
    }
    __syncthreads();

    for (int l = 0; l < L_; l++) {
        ln32(X, XN, ln1g + l*H_, ln1b + l*H_, tid);
        __syncthreads();
        mm32<768, 256, 0>(XN, qkvW + (size_t)l*3*H_*H_, qkvb + l*3*H_, BUF, tid);
        __syncthreads();
        attn32(BUF, BS, KM, XN, tid);
        __syncthreads();
        mm32<256, 256, 2>(XN, outW + (size_t)l*H_*H_, outb + l*H_, X, tid);
        __syncthreads();
        ln32(X, XN, ln2g + l*H_, ln2b + l*H_, tid);
        __syncthreads();
        mm32<512, 256, 1>(XN, ff1W + (size_t)l*FFN_*H_, ff1b + l*FFN_, BUF, tid);
        __syncthreads();
        mm32<256, 512, 2>(BUF, ff2W + (size_t)l*H_*FFN_, ff2b + l*H_, X, tid);
        __syncthreads();
    }

    // final LN + masked mean over k
    ln32(X, XN, fng, fnb, tid);
    __syncthreads();
    float sum = 0.f, cnt = 0.f;
    #pragma unroll
    for (int r = 0; r < K_; r++) {
        sum = fmaf(XN[r*H_ + tid], V01[r], sum);
        cnt += V01[r];
    }
    out[(size_t)s*H_ + tid] = sum / fmaxf(cnt, 1.f);
}

// ---------------------------------------------------------------------------
extern "C" void kernel_launch(void* const* d_in, const int* in_sizes, int n_in,
                              void* d_out, int out_size)
{
    // inputs: 0 h, 1 valid, 2 edge_index, 3 ea_flat, 4 edge_ptr, 5 S, 6 k,
    // 7 edge_W, 8 edge_b, 9 ln1_g, 10 ln1_b, 11 qkv_W, 12 qkv_b, 13 out_W,
    // 14 out_b, 15 ln2_g, 16 ln2_b, 17 ff1_W, 18 ff1_b, 19 ff2_W, 20 ff2_b,
    // 21 fnorm_g, 22 fnorm_b
    cudaFuncSetAttribute(xf_kernel, cudaFuncAttributeMaxDynamicSharedMemorySize,
                         SMEM2_FLOATS * (int)sizeof(float));

    edge_bias_kernel<<<S_, 256>>>(
        (const float*)d_in[3], (const int*)d_in[2],
        (const float*)d_in[7], (const float*)d_in[8]);

    xf_kernel<<<S_, 256, SMEM2_FLOATS * sizeof(float)>>>(
        (const float*)d_in[0], d_in[1],
        (const float*)d_in[9],  (const float*)d_in[10],
        (const float*)d_in[11], (const float*)d_in[12],
        (const float*)d_in[13], (const float*)d_in[14],
        (const float*)d_in[15], (const float*)d_in[16],
        (const float*)d_in[17], (const float*)d_in[18],
        (const float*)d_in[19], (const float*)d_in[20],
        (const float*)d_in[21], (const float*)d_in[22],
        (float*)d_out);
}

// round 3
// speedup vs baseline: 4.2735x; 4.2735x over previous
#include <cuda_runtime.h>
#include <cuda_bf16.h>
#include <math.h>

// Problem constants (LocalSubgraphTransformer)
#define S_   2048
#define K_   32
#define H_   256
#define NH_  8
#define DH_  32
#define L_   4
#define ED_  16
#define FFN_ 512
#define EPS_ 64
#define E_   (S_*EPS_)
#define BUFLD 768

// 32 MB scratch: edge bias [S][h][k=dst][q=src] in bf16
__device__ __nv_bfloat16 g_bias16[(size_t)S_ * NH_ * K_ * K_];

// ---------------------------------------------------------------------------
// Kernel A: per-subgraph edge bias via shared-memory scatter-add
// ---------------------------------------------------------------------------
__global__ __launch_bounds__(256) void edge_bias_kernel(
    const float* __restrict__ ea, const int* __restrict__ eidx,
    const float* __restrict__ eW, const float* __restrict__ eb)
{
    __shared__ float sb[NH_*K_*K_];   // [h][dst][src]
    __shared__ float sa[EPS_*ED_];
    __shared__ float sw[NH_*ED_];
    __shared__ float sbv[NH_];
    const int s = blockIdx.x, tid = threadIdx.x;

    if (tid < NH_*ED_) sw[tid] = eW[tid];
    if (tid < NH_)     sbv[tid] = eb[tid];
    for (int i = tid; i < EPS_*ED_;  i += 256) sa[i] = ea[(size_t)s*EPS_*ED_ + i];
    for (int i = tid; i < NH_*K_*K_; i += 256) sb[i] = 0.f;
    __syncthreads();

    #pragma unroll
    for (int t = tid; t < EPS_*NH_; t += 256) {
        const int i  = t >> 3;    // edge within subgraph
        const int hh = t & 7;     // head
        float p = sbv[hh];
        #pragma unroll
        for (int d = 0; d < ED_; d++) p = fmaf(sa[i*ED_+d], sw[hh*ED_+d], p);
        const int e  = s*EPS_ + i;
        const int sr = eidx[e];        // src = query index
        const int ds = eidx[E_ + e];   // dst = key index
        atomicAdd(&sb[hh*K_*K_ + ds*K_ + sr], p);
    }
    __syncthreads();
    for (int i = tid; i < NH_*K_*K_; i += 256)
        g_bias16[(size_t)s*NH_*K_*K_ + i] = __float2bfloat16(sb[i]);
}

// ---------------------------------------------------------------------------
// Kernel B: fused 4-layer transformer, one CTA per subgraph
// ---------------------------------------------------------------------------
// smem layout (float offsets)
#define OFF_X    0       /* 8192 */
#define OFF_XN   8192    /* 8192 */
#define OFF_BUF  16384   /* 24576: qkv [32][768] or ffn hidden [32][512] */
#define OFF_WT   40960   /* 8192: double-buffered W tile 2 x [128][32] swizzled */
#define OFF_BS16 49152   /* bf16[8192] = 4096 floats: bias [h][k][q] */
#define OFF_KM   53248   /* 32 */
#define OFF_V01  53280   /* 32 */
#define SMEM_FLOATS 53312

__device__ __forceinline__ void ffma2(unsigned long long& c,
                                      unsigned long long a, unsigned long long b) {
    asm("fma.rn.f32x2 %0, %1, %2, %0;" : "+l"(c) : "l"(a), "l"(b));
}

// C[32,N] = A[32,KA] @ W[N,KA]^T + bias ; MODE 0: store, 1: store+relu, 2: dst += C
// A: smem [32][KA]; W: global, staged through swizzled smem tiles via cp.async.
template<int N, int KA, int MODE>
__device__ __forceinline__ void mm32(const float* A, const float* __restrict__ W,
                                     const float* __restrict__ bias, float* dst,
                                     float* WT, int tid)
{
    const int rg = tid >> 5;   // warp -> rows rg*4..rg*4+3
    const int cg = tid & 31;   // lane -> 4 columns
    const int sw = cg & 7;
    const unsigned wt_s = (unsigned)__cvta_generic_to_shared(WT);
    constexpr int T = KA/32;   // k-tiles per pass

    for (int pass = 0; pass < N/128; pass++) {
        const float* Wp = W + (size_t)pass*128*KA;
        // prefetch tile 0 -> buffer 0
        #pragma unroll
        for (int it = 0; it < 4; it++) {
            const int v = it*256 + tid, cr = v >> 3, k4 = v & 7;
            const unsigned d = wt_s + (unsigned)((cr*32 + ((k4 ^ ((cr>>2)&7))<<2))*4);
            const float* g = Wp + cr*KA + k4*4;
            asm volatile("cp.async.cg.shared.global [%0], [%1], 16;" :: "r"(d), "l"(g) : "memory");
        }
        asm volatile("cp.async.commit_group;" ::: "memory");

        unsigned long long acc[4][4];
        #pragma unroll
        for (int j = 0; j < 4; j++)
            #pragma unroll
            for (int i = 0; i < 4; i++) acc[j][i] = 0ull;

        for (int kt = 0; kt < T; kt++) {
            asm volatile("cp.async.wait_group 0;" ::: "memory");
            __syncthreads();
            if (kt + 1 < T) {  // prefetch next tile into other buffer
                const float* Wn = Wp + (kt+1)*32;
                const unsigned bufn = ((kt+1) & 1) ? 4096u*4u : 0u;
                #pragma unroll
                for (int it = 0; it < 4; it++) {
                    const int v = it*256 + tid, cr = v >> 3, k4 = v & 7;
                    const unsigned d = wt_s + bufn +
                        (unsigned)((cr*32 + ((k4 ^ ((cr>>2)&7))<<2))*4);
                    const float* g = Wn + cr*KA + k4*4;
                    asm volatile("cp.async.cg.shared.global [%0], [%1], 16;" :: "r"(d), "l"(g) : "memory");
                }
                asm volatile("cp.async.commit_group;" ::: "memory");
            }
            const float* WTc = WT + ((kt & 1) ? 4096 : 0);
            const float* Ac  = A + kt*32;
            #pragma unroll
            for (int t8 = 0; t8 < 8; t8++) {
                ulonglong2 a[4], w[4];
                #pragma unroll
                for (int j = 0; j < 4; j++)   // broadcast (conflict-free)
                    a[j] = *(const ulonglong2*)(Ac + (rg*4+j)*KA + t8*4);
                #pragma unroll
                for (int i = 0; i < 4; i++)   // swizzled (phase-conflict-free)
                    w[i] = *(const ulonglong2*)(WTc + (cg*4+i)*32 + ((t8 ^ sw)<<2));
                #pragma unroll
                for (int j = 0; j < 4; j++)
                    #pragma unroll
                    for (int i = 0; i < 4; i++) {
                        ffma2(acc[j][i], a[j].x, w[i].x);
                        ffma2(acc[j][i], a[j].y, w[i].y);
                    }
            }
        }
        // epilogue
        const int c0 = pass*128 + cg*4;
        #pragma unroll
        for (int j = 0; j < 4; j++) {
            float4 r;
            float* rp = (float*)&r;
            #pragma unroll
            for (int i = 0; i < 4; i++) {
                float lo, hi;
                asm("mov.b64 {%0,%1}, %2;" : "=f"(lo), "=f"(hi) : "l"(acc[j][i]));
                rp[i] = lo + hi + bias[c0+i];
            }
            if (MODE == 1) {
                r.x = fmaxf(r.x, 0.f); r.y = fmaxf(r.y, 0.f);
                r.z = fmaxf(r.z, 0.f); r.w = fmaxf(r.w, 0.f);
            }
            float4* p = (float4*)(dst + (rg*4+j)*N + c0);
            if (MODE == 2) {
                float4 o = *p;
                r.x += o.x; r.y += o.y; r.z += o.z; r.w += o.w;
            }
            *p = r;
        }
    }
}

// LayerNorm over 32 rows of H_: warp w handles rows w*4..w*4+3
__device__ __forceinline__ void ln32(const float* src, float* dst,
                                     const float* __restrict__ g,
                                     const float* __restrict__ b, int tid)
{
    const int w = tid >> 5, lane = tid & 31;
    #pragma unroll
    for (int j = 0; j < 4; j++) {
        const int r = w*4 + j;
        float sum = 0.f, sq = 0.f;
        #pragma unroll
        for (int i = 0; i < 8; i++) {
            const float v = src[r*H_ + lane + i*32];
            sum += v; sq = fmaf(v, v, sq);
        }
        #pragma unroll
        for (int o = 16; o > 0; o >>= 1) {
            sum += __shfl_xor_sync(0xffffffffu, sum, o);
            sq  += __shfl_xor_sync(0xffffffffu, sq,  o);
        }
        const float mu   = sum * (1.f/H_);
        const float var  = sq * (1.f/H_) - mu*mu;
        const float rstd = rsqrtf(var + 1e-5f);
        #pragma unroll
        for (int i = 0; i < 8; i++) {
            const int c = lane + i*32;
            const float v = src[r*H_ + c];
            dst[r*H_ + c] = fmaf((v - mu)*rstd, g[c], b[c]);
        }
    }
}

// Attention: warp = head, lane = query row. qkv in BUF (ld 768), o -> XN (ld 256)
__device__ __forceinline__ void attn32(const float* BUF_, const __nv_bfloat16* BS,
                                       const float* KM, float* XN_, int tid)
{
    const int head = tid >> 5, lane = tid & 31;
    const float scale = 0.17677669529663687f;  // 1/sqrt(32)

    float4 q4[8];
    const float4* qp = (const float4*)(BUF_ + lane*BUFLD + head*32);
    #pragma unroll
    for (int j = 0; j < 8; j++) q4[j] = qp[j];

    float sc[32];
    float m = -3.0e38f;
    #pragma unroll
    for (int kr = 0; kr < 32; kr++) {
        const float4* kp = (const float4*)(BUF_ + kr*BUFLD + H_ + head*32);
        float s = 0.f;
        #pragma unroll
        for (int j = 0; j < 8; j++) {
            const float4 kk = kp[j];
            s = fmaf(q4[j].x, kk.x, s); s = fmaf(q4[j].y, kk.y, s);
            s = fmaf(q4[j].z, kk.z, s); s = fmaf(q4[j].w, kk.w, s);
        }
        const float bv = __bfloat162float(BS[head*1024 + kr*32 + lane]);
        s = fmaf(s, scale, bv) + KM[kr];
        sc[kr] = s;
        m = fmaxf(m, s);
    }
    float den = 0.f;
    #pragma unroll
    for (int kr = 0; kr < 32; kr++) { const float e = __expf(sc[kr] - m); sc[kr] = e; den += e; }
    const float inv = 1.f / den;
    #pragma unroll
    for (int kr = 0; kr < 32; kr++) sc[kr] *= inv;

    #pragma unroll
    for (int dg = 0; dg < 8; dg++) {
        float4 acc = make_float4(0.f, 0.f, 0.f, 0.f);
        #pragma unroll
        for (int kr = 0; kr < 32; kr++) {
            const float4 v4 = *(const float4*)(BUF_ + kr*BUFLD + 2*H_ + head*32 + dg*4);
            const float w = sc[kr];
            acc.x = fmaf(w, v4.x, acc.x); acc.y = fmaf(w, v4.y, acc.y);
            acc.z = fmaf(w, v4.z, acc.z); acc.w = fmaf(w, v4.w, acc.w);
        }
        *(float4*)(XN_ + lane*H_ + head*32 + dg*4) = acc;
    }
}

__global__ __launch_bounds__(256, 1) void xf_kernel(
    const float* __restrict__ h, const void* __restrict__ validp,
    const float* __restrict__ ln1g, const float* __restrict__ ln1b,
    const float* __restrict__ qkvW, const float* __restrict__ qkvb,
    const float* __restrict__ outW, const float* __restrict__ outb,
    const float* __restrict__ ln2g, const float* __restrict__ ln2b,
    const float* __restrict__ ff1W, const float* __restrict__ ff1b,
    const float* __restrict__ ff2W, const float* __restrict__ ff2b,
    const float* __restrict__ fng, const float* __restrict__ fnb,
    float* __restrict__ out)
{
    extern __shared__ float sm[];
    float* X   = sm + OFF_X;
    float* XN  = sm + OFF_XN;
    float* BUF = sm + OFF_BUF;
    float* WT  = sm + OFF_WT;
    __nv_bfloat16* BS16 = (__nv_bfloat16*)(sm + OFF_BS16);
    float* KM  = sm + OFF_KM;
    float* V01 = sm + OFF_V01;
    const int s = blockIdx.x, tid = threadIdx.x;

    // Detect 'valid' encoding: byte bools vs 32-bit words.
    const unsigned char* vb = (const unsigned char*)validp;
    bool bytemode = false;
    #pragma unroll
    for (int i = 1; i < 128; i += 4) bytemode |= (vb[i] != 0);

    if (tid < K_) {
        bool v;
        if (bytemode) v = vb[s*K_ + tid] != 0;
        else          v = ((const unsigned int*)validp)[s*K_ + tid] != 0u;
        KM[tid]  = v ? 0.f : -1e30f;
        V01[tid] = v ? 1.f : 0.f;
    }
    for (int i = tid; i < K_*H_/4; i += 256)
        ((float4*)X)[i] = ((const float4*)(h + (size_t)s*K_*H_))[i];
    // bias already [h][k][q] bf16: straight vector copy (1024 uint4)
    {
        const uint4* gb = (const uint4*)(g_bias16 + (size_t)s*NH_*K_*K_);
        uint4* sb = (uint4*)BS16;
        for (int i = tid; i < 1024; i += 256) sb[i] = gb[i];
    }
    __syncthreads();

    for (int l = 0; l < L_; l++) {
        ln32(X, XN, ln1g + l*H_, ln1b + l*H_, tid);
        __syncthreads();
        mm32<768, 256, 0>(XN, qkvW + (size_t)l*3*H_*H_, qkvb + l*3*H_, BUF, WT, tid);
        __syncthreads();
        attn32(BUF, BS16, KM, XN, tid);
        __syncthreads();
        mm32<256, 256, 2>(XN, outW + (size_t)l*H_*H_, outb + l*H_, X, WT, tid);
        __syncthreads();
        ln32(X, XN, ln2g + l*H_, ln2b + l*H_, tid);
        __syncthreads();
        mm32<512, 256, 1>(XN, ff1W + (size_t)l*FFN_*H_, ff1b + l*FFN_, BUF, WT, tid);
        __syncthreads();
        mm32<256, 512, 2>(BUF, ff2W + (size_t)l*H_*FFN_, ff2b + l*H_, X, WT, tid);
        __syncthreads();
    }

    // final LN + masked mean over k
    ln32(X, XN, fng, fnb, tid);
    __syncthreads();
    float sum = 0.f, cnt = 0.f;
    #pragma unroll
    for (int r = 0; r < K_; r++) {
        sum = fmaf(XN[r*H_ + tid], V01[r], sum);
        cnt += V01[r];
    }
    out[(size_t)s*H_ + tid] = sum / fmaxf(cnt, 1.f);
}

// ---------------------------------------------------------------------------
extern "C" void kernel_launch(void* const* d_in, const int* in_sizes, int n_in,
                              void* d_out, int out_size)
{
    // inputs: 0 h, 1 valid, 2 edge_index, 3 ea_flat, 4 edge_ptr, 5 S, 6 k,
    // 7 edge_W, 8 edge_b, 9 ln1_g, 10 ln1_b, 11 qkv_W, 12 qkv_b, 13 out_W,
    // 14 out_b, 15 ln2_g, 16 ln2_b, 17 ff1_W, 18 ff1_b, 19 ff2_W, 20 ff2_b,
    // 21 fnorm_g, 22 fnorm_b
    cudaFuncSetAttribute(xf_kernel, cudaFuncAttributeMaxDynamicSharedMemorySize,
                         SMEM_FLOATS * (int)sizeof(float));

    edge_bias_kernel<<<S_, 256>>>(
        (const float*)d_in[3], (const int*)d_in[2],
        (const float*)d_in[7], (const float*)d_in[8]);

    xf_kernel<<<S_, 256, SMEM_FLOATS * sizeof(float)>>>(
        (const float*)d_in[0], d_in[1],
        (const float*)d_in[9],  (const float*)d_in[10],
        (const float*)d_in[11], (const float*)d_in[12],
        (const float*)d_in[13], (const float*)d_in[14],
        (const float*)d_in[15], (const float*)d_in[16],
        (const float*)d_in[17], (const float*)d_in[18],
        (const float*)d_in[19], (const float*)d_in[20],
        (const float*)d_in[21], (const float*)d_in[22],
        (float*)d_out);
}